// round 14
// baseline (speedup 1.0000x reference)
#include <cuda_runtime.h>

// GlimpseSensor: extract P=3 patches (sizes 64,128,256) centered at l, nearest-
// downsample each to 64x64. Pure gather, zero-fill out of bounds.
// Shapes fixed: x (64,3,512,512) f32, l (64,2) f32, out (64,3,3,64,64) f32.
//
// R11: latency-bound fix. Each thread produces 8 outputs (4 rows x 2 cols)
// with all 8 LDGs front-batched (MLP=8). Grid decode moved to blockIdx
// (z=b, y=p*C+c, x=row-group) so no per-thread div/mod. Lane-adjacent input
// columns keep warp loads at minimal sector counts (5/9/17 for p=0/1/2).

#define B_   64
#define C_   3
#define H_   512
#define W_   512
#define P_   3
#define DS_  64
#define ROWS_PER_THREAD 4

__global__ void __launch_bounds__(256) glimpse_kernel(
    const float* __restrict__ x,
    const float* __restrict__ l,
    float* __restrict__ out)
{
    const int lane = threadIdx.x & 31;
    const int w    = threadIdx.x >> 5;          // warp in block, 0..7
    const int b    = blockIdx.z;                // 0..63
    const int pc   = blockIdx.y;                // p*C + c, 0..8
    const int p    = pc / 3;                    // uniform per block
    const int c    = pc - 3 * p;

    const int stride = 1 << p;                  // size / ds
    const int half   = 32 << p;                 // size / 2

    const float lr = __ldg(&l[2 * b]);
    const float lc = __ldg(&l[2 * b + 1]);
    // match jnp.floor(0.5 * (l + 1.0) * H) exactly (fp32, same op order)
    const int base_r = (int)floorf((0.5f * (lr + 1.0f)) * (float)H_) - half;
    const int base_c = (int)floorf((0.5f * (lc + 1.0f)) * (float)H_) - half;

    // columns handled by this lane (loop-invariant across rows)
    const int icol0 = base_c + lane * stride;
    const int icol1 = icol0 + 32 * stride;
    const bool c0ok = (icol0 >= 0) & (icol0 < W_);
    const bool c1ok = (icol1 >= 0) & (icol1 < W_);

    const int r0 = blockIdx.x * 32 + w * ROWS_PER_THREAD;   // first output row
    const float* __restrict__ xplane = x + (size_t)(b * C_ + c) * (H_ * W_);

    float v0[ROWS_PER_THREAD], v1[ROWS_PER_THREAD];

    // ---- load phase: 8 independent LDGs, front-batched ----
    #pragma unroll
    for (int i = 0; i < ROWS_PER_THREAD; ++i) {
        int row = base_r + (r0 + i) * stride;
        bool rok = (row >= 0) & (row < H_);
        const float* __restrict__ xrow = xplane + (size_t)(rok ? row : 0) * W_;
        v0[i] = (rok & c0ok) ? __ldg(xrow + icol0) : 0.0f;
        v1[i] = (rok & c1ok) ? __ldg(xrow + icol1) : 0.0f;
    }

    // ---- store phase: fully coalesced ----
    // out element index: ((b*9 + pc)*64 + r)*64 + col
    const int t2 = b * 9 + pc;
    #pragma unroll
    for (int i = 0; i < ROWS_PER_THREAD; ++i) {
        int obase = (((t2 << 6) + (r0 + i)) << 6);
        out[obase + lane]      = v0[i];
        out[obase + lane + 32] = v1[i];
    }
}

extern "C" void kernel_launch(void* const* d_in, const int* in_sizes, int n_in,
                              void* d_out, int out_size)
{
    const float* x = (const float*)d_in[0];
    const float* l = (const float*)d_in[1];
    float* out = (float*)d_out;

    // grid: x = row-groups (64 rows / (8 warps * 4 rows) = 2), y = p*C+c, z = b
    dim3 grid(2, P_ * C_, B_);   // 1152 blocks
    glimpse_kernel<<<grid, 256>>>(x, l, out);
}

// round 15
// speedup vs baseline: 1.0257x; 1.0257x over previous
#include <cuda_runtime.h>

// GlimpseSensor: extract P=3 patches (sizes 64,128,256) centered at l, nearest-
// downsample each to 64x64. Pure gather, zero-fill out of bounds.
// Shapes fixed: x (64,3,512,512) f32, l (64,2) f32, out (64,3,3,64,64) f32.
//
// R11: latency-bound fix. Each thread produces 8 outputs (4 rows x 2 cols)
// with all 8 LDGs front-batched (MLP=8). Grid decode moved to blockIdx
// (z=b, y=p*C+c, x=row-group) so no per-thread div/mod. Lane-adjacent input
// columns keep warp loads at minimal sector counts (5/9/17 for p=0/1/2).

#define B_   64
#define C_   3
#define H_   512
#define W_   512
#define P_   3
#define DS_  64
#define ROWS_PER_THREAD 4

__global__ void __launch_bounds__(256) glimpse_kernel(
    const float* __restrict__ x,
    const float* __restrict__ l,
    float* __restrict__ out)
{
    const int lane = threadIdx.x & 31;
    const int w    = threadIdx.x >> 5;          // warp in block, 0..7
    const int b    = blockIdx.z;                // 0..63
    const int pc   = blockIdx.y;                // p*C + c, 0..8
    const int p    = pc / 3;                    // uniform per block
    const int c    = pc - 3 * p;

    const int stride = 1 << p;                  // size / ds
    const int half   = 32 << p;                 // size / 2

    const float lr = __ldg(&l[2 * b]);
    const float lc = __ldg(&l[2 * b + 1]);
    // match jnp.floor(0.5 * (l + 1.0) * H) exactly (fp32, same op order)
    const int base_r = (int)floorf((0.5f * (lr + 1.0f)) * (float)H_) - half;
    const int base_c = (int)floorf((0.5f * (lc + 1.0f)) * (float)H_) - half;

    // columns handled by this lane (loop-invariant across rows)
    const int icol0 = base_c + lane * stride;
    const int icol1 = icol0 + 32 * stride;
    const bool c0ok = (icol0 >= 0) & (icol0 < W_);
    const bool c1ok = (icol1 >= 0) & (icol1 < W_);

    const int r0 = blockIdx.x * 32 + w * ROWS_PER_THREAD;   // first output row
    const float* __restrict__ xplane = x + (size_t)(b * C_ + c) * (H_ * W_);

    float v0[ROWS_PER_THREAD], v1[ROWS_PER_THREAD];

    // ---- load phase: 8 independent LDGs, front-batched ----
    #pragma unroll
    for (int i = 0; i < ROWS_PER_THREAD; ++i) {
        int row = base_r + (r0 + i) * stride;
        bool rok = (row >= 0) & (row < H_);
        const float* __restrict__ xrow = xplane + (size_t)(rok ? row : 0) * W_;
        v0[i] = (rok & c0ok) ? __ldg(xrow + icol0) : 0.0f;
        v1[i] = (rok & c1ok) ? __ldg(xrow + icol1) : 0.0f;
    }

    // ---- store phase: fully coalesced ----
    // out element index: ((b*9 + pc)*64 + r)*64 + col
    const int t2 = b * 9 + pc;
    #pragma unroll
    for (int i = 0; i < ROWS_PER_THREAD; ++i) {
        int obase = (((t2 << 6) + (r0 + i)) << 6);
        out[obase + lane]      = v0[i];
        out[obase + lane + 32] = v1[i];
    }
}

extern "C" void kernel_launch(void* const* d_in, const int* in_sizes, int n_in,
                              void* d_out, int out_size)
{
    const float* x = (const float*)d_in[0];
    const float* l = (const float*)d_in[1];
    float* out = (float*)d_out;

    // grid: x = row-groups (64 rows / (8 warps * 4 rows) = 2), y = p*C+c, z = b
    dim3 grid(2, P_ * C_, B_);   // 1152 blocks
    glimpse_kernel<<<grid, 256>>>(x, l, out);
}

// round 16
// speedup vs baseline: 1.0649x; 1.0382x over previous
#include <cuda_runtime.h>

// GlimpseSensor: extract P=3 patches (sizes 64,128,256) centered at l, nearest-
// downsample each to 64x64. Pure gather, zero-fill out of bounds.
// Shapes fixed: x (64,3,512,512) f32, l (64,2) f32, out (64,3,3,64,64) f32.
//
// R11: latency-bound fix. Each thread produces 8 outputs (4 rows x 2 cols)
// with all 8 LDGs front-batched (MLP=8). Grid decode moved to blockIdx
// (z=b, y=p*C+c, x=row-group) so no per-thread div/mod. Lane-adjacent input
// columns keep warp loads at minimal sector counts (5/9/17 for p=0/1/2).

#define B_   64
#define C_   3
#define H_   512
#define W_   512
#define P_   3
#define DS_  64
#define ROWS_PER_THREAD 4

__global__ void __launch_bounds__(256) glimpse_kernel(
    const float* __restrict__ x,
    const float* __restrict__ l,
    float* __restrict__ out)
{
    const int lane = threadIdx.x & 31;
    const int w    = threadIdx.x >> 5;          // warp in block, 0..7
    const int b    = blockIdx.z;                // 0..63
    const int pc   = blockIdx.y;                // p*C + c, 0..8
    const int p    = pc / 3;                    // uniform per block
    const int c    = pc - 3 * p;

    const int stride = 1 << p;                  // size / ds
    const int half   = 32 << p;                 // size / 2

    const float lr = __ldg(&l[2 * b]);
    const float lc = __ldg(&l[2 * b + 1]);
    // match jnp.floor(0.5 * (l + 1.0) * H) exactly (fp32, same op order)
    const int base_r = (int)floorf((0.5f * (lr + 1.0f)) * (float)H_) - half;
    const int base_c = (int)floorf((0.5f * (lc + 1.0f)) * (float)H_) - half;

    // columns handled by this lane (loop-invariant across rows)
    const int icol0 = base_c + lane * stride;
    const int icol1 = icol0 + 32 * stride;
    const bool c0ok = (icol0 >= 0) & (icol0 < W_);
    const bool c1ok = (icol1 >= 0) & (icol1 < W_);

    const int r0 = blockIdx.x * 32 + w * ROWS_PER_THREAD;   // first output row
    const float* __restrict__ xplane = x + (size_t)(b * C_ + c) * (H_ * W_);

    float v0[ROWS_PER_THREAD], v1[ROWS_PER_THREAD];

    // ---- load phase: 8 independent LDGs, front-batched ----
    #pragma unroll
    for (int i = 0; i < ROWS_PER_THREAD; ++i) {
        int row = base_r + (r0 + i) * stride;
        bool rok = (row >= 0) & (row < H_);
        const float* __restrict__ xrow = xplane + (size_t)(rok ? row : 0) * W_;
        v0[i] = (rok & c0ok) ? __ldg(xrow + icol0) : 0.0f;
        v1[i] = (rok & c1ok) ? __ldg(xrow + icol1) : 0.0f;
    }

    // ---- store phase: fully coalesced ----
    // out element index: ((b*9 + pc)*64 + r)*64 + col
    const int t2 = b * 9 + pc;
    #pragma unroll
    for (int i = 0; i < ROWS_PER_THREAD; ++i) {
        int obase = (((t2 << 6) + (r0 + i)) << 6);
        out[obase + lane]      = v0[i];
        out[obase + lane + 32] = v1[i];
    }
}

extern "C" void kernel_launch(void* const* d_in, const int* in_sizes, int n_in,
                              void* d_out, int out_size)
{
    const float* x = (const float*)d_in[0];
    const float* l = (const float*)d_in[1];
    float* out = (float*)d_out;

    // grid: x = row-groups (64 rows / (8 warps * 4 rows) = 2), y = p*C+c, z = b
    dim3 grid(2, P_ * C_, B_);   // 1152 blocks
    glimpse_kernel<<<grid, 256>>>(x, l, out);
}